// round 13
// baseline (speedup 1.0000x reference)
#include <cuda_runtime.h>
#include <cuda_bf16.h>
#include <cstdint>

#define KC 512
#define DD 64
#define HW 4096
#define NVEC 131072
#define NTH 128
#define MTILE 128
#define NTILES (NVEC / MTILE)        // 1024
#define GRID 128                     // 8 tiles per CTA, perfectly balanced

// smem byte offsets
#define OFF_CBSQR  0                         // 512 f32 = 2048
#define OFF_SMIN   2048                      // 128 f32 = 512
#define OFF_MAXB   2560                      // 4B
#define OFF_CB16   2688                      // 512 rows * 36 u32 = 73728
#define OFF_A16    (2688 + 73728)            // 128 rows * 36 u32 = 18432
#define OFF_SBUF   (OFF_A16 + 18432)         // 128 rows * 261 u32 = 133632
#define SROW_U32   261                       // 256 data + 5 pad (stride mod 32 = 5)
#define CBROW_U32  36                        // 32 data + 4 pad (4g+t bank map)
#define SMEM_TOTAL (OFF_SBUF + 128 * SROW_U32 * 4)   // 228480 <= 232448

typedef unsigned long long u64;
typedef unsigned int u32;

__device__ __forceinline__ u64 ffma2(u64 a, u64 b, u64 c) {
    u64 d;
    asm("fma.rn.f32x2 %0, %1, %2, %3;" : "=l"(d) : "l"(a), "l"(b), "l"(c));
    return d;
}
__device__ __forceinline__ u64 pk(float lo, float hi) {
    u64 d;
    asm("mov.b64 %0, {%1, %2};" : "=l"(d) : "f"(lo), "f"(hi));
    return d;
}
__device__ __forceinline__ void unpack2(u64 a, float& lo, float& hi) {
    asm("mov.b64 {%0, %1}, %2;" : "=f"(lo), "=f"(hi) : "l"(a));
}
__device__ __forceinline__ u32 bf16x2(float hi, float lo) {
    u32 w;
    asm("cvt.rn.bf16x2.f32 %0, %1, %2;" : "=r"(w) : "f"(hi), "f"(lo));
    return w;
}
// Scalar tree identical to round 1 (bit-exact vs reference; rel_err 0.0).
__device__ __forceinline__ float tree8(u64 a0, u64 a1, u64 a2, u64 a3) {
    float f0, f1, f2, f3, f4, f5, f6, f7;
    unpack2(a0, f0, f1); unpack2(a1, f2, f3);
    unpack2(a2, f4, f5); unpack2(a3, f6, f7);
    return ((f0 + f1) + (f2 + f3)) + ((f4 + f5) + (f6 + f7));
}
// Exact distance: byte-identical arithmetic to round 1 (4 chains, tree, fmaf).
__device__ __forceinline__ float exact_dist(const float* __restrict__ cbrow,
                                            const u64* x2, float ckxs) {
    u64 a0 = 0, a1 = 0, a2 = 0, a3 = 0;
    const float4* c4 = (const float4*)cbrow;
    #pragma unroll
    for (int j = 0; j < 8; j++) {
        float4 lo = c4[2 * j], hi = c4[2 * j + 1];
        a0 = ffma2(x2[4 * j + 0], pk(lo.x, lo.y), a0);
        a1 = ffma2(x2[4 * j + 1], pk(lo.z, lo.w), a1);
        a2 = ffma2(x2[4 * j + 2], pk(hi.x, hi.y), a2);
        a3 = ffma2(x2[4 * j + 3], pk(hi.z, hi.w), a3);
    }
    return fmaf(-2.0f, tree8(a0, a1, a2, a3), ckxs);
}
// HMMA m16n8k16 bf16 -> f32, D += A.B  (plain PTX, sm_80+, no 'a' features)
__device__ __forceinline__ void mma16816(float* d, const u32* a, u32 b0, u32 b1) {
    asm volatile(
        "mma.sync.aligned.m16n8k16.row.col.f32.bf16.bf16.f32 "
        "{%0,%1,%2,%3}, {%4,%5,%6,%7}, {%8,%9}, {%0,%1,%2,%3};"
        : "+f"(d[0]), "+f"(d[1]), "+f"(d[2]), "+f"(d[3])
        : "r"(a[0]), "r"(a[1]), "r"(a[2]), "r"(a[3]), "r"(b0), "r"(b1));
}

__global__ void __launch_bounds__(NTH, 1)
vq_kernel(const float* __restrict__ ze, const float* __restrict__ cbg,
          float* __restrict__ out, int write2) {
    extern __shared__ char smem[];
    float* cbsqr   = (float*)(smem + OFF_CBSQR);
    float* sminbuf = (float*)(smem + OFF_SMIN);
    int*   maxb    = (int*)(smem + OFF_MAXB);
    u32*   cb16    = (u32*)(smem + OFF_CB16);   // [512][36]
    u32*   a16     = (u32*)(smem + OFF_A16);    // [128][36]
    u32*   sbuf    = (u32*)(smem + OFF_SBUF);   // [128][261]

    const int tid = threadIdx.x;
    const int wid = tid >> 5;
    const int lane = tid & 31;
    const int g = lane >> 2;        // mma group row
    const int t = lane & 3;         // mma thread-in-group

    // ---- setup: codebook bf16 (padded rows), cbsqr, cmax ----
    if (tid == 0) *maxb = 0;
    __syncthreads();
    for (int idx = tid; idx < KC * 32; idx += NTH) {
        int row = idx >> 5, j = idx & 31;
        float lo = cbg[row * DD + 2 * j], hi = cbg[row * DD + 2 * j + 1];
        cb16[row * CBROW_U32 + j] = bf16x2(hi, lo);
    }
    for (int k = tid; k < KC; k += NTH) {
        const float* row = cbg + k * DD;
        float s = 0.f;
        #pragma unroll
        for (int d = 0; d < DD; d++) s = fmaf(row[d], row[d], s);
        cbsqr[k] = s;
        atomicMax(maxb, __float_as_int(s));   // s > 0: bits monotone
    }
    __syncthreads();
    const float cmax = sqrtf(__int_as_float(*maxb)) * 1.0002f;

    const int m = tid;                 // vector slot in tile / sbuf row
    const int wbase = wid * 32;        // this warp's row block

    for (int tile = blockIdx.x; tile < NTILES; tile += GRID) {
        const int n = tile * MTILE + m;
        const int b = n >> 12;
        const int s = n & 4095;        // all rows in tile share b (128 | 4096)
        const float* xp = ze + (size_t)b * (DD * HW) + s;

        // ---- load x (f32), xsqr (round-1 chain), pack regs, A row bf16 ----
        u64 x2[32];
        float xsqr = 0.f;
        #pragma unroll
        for (int j = 0; j < 32; j++) {
            float lo = xp[(size_t)(2 * j) * HW];
            float hi = xp[(size_t)(2 * j + 1) * HW];
            xsqr = fmaf(lo, lo, xsqr);
            xsqr = fmaf(hi, hi, xsqr);
            x2[j] = pk(lo, hi);
        }
        {
            u32* arow = a16 + m * CBROW_U32;
            #pragma unroll
            for (int jj = 0; jj < 32; jj++) {     // rotation: conflict-free STS
                int j = (jj + m) & 31;
                float lo, hi;
                unpack2(x2[j], lo, hi);
                arow[j] = bf16x2(hi, lo);
            }
        }
        __syncwarp();   // A rows are warp-private (warp w owns rows 32w..32w+31)

        // ---- register-resident A fragments: af[mtile][kstep][4] ----
        u32 af[2][4][4];
        #pragma unroll
        for (int mt = 0; mt < 2; mt++) {
            const u32* r0 = a16 + (wbase + mt * 16 + g) * CBROW_U32;
            const u32* r1 = r0 + 8 * CBROW_U32;
            #pragma unroll
            for (int ks = 0; ks < 4; ks++) {
                af[mt][ks][0] = r0[ks * 8 + t];
                af[mt][ks][1] = r1[ks * 8 + t];
                af[mt][ks][2] = r0[ks * 8 + t + 4];
                af[mt][ks][3] = r1[ks * 8 + t + 4];
            }
        }

        // ---- mma loop: 64 N-tiles of 8 codes; s = ck - 2 dot -> bf16 ----
        float mn0 = 3.4e38f, mn1 = 3.4e38f, mn2 = 3.4e38f, mn3 = 3.4e38f;
        #pragma unroll 2
        for (int nt = 0; nt < 64; nt++) {
            const u32* bw = cb16 + (nt * 8 + g) * CBROW_U32;
            float d0[4] = {0.f, 0.f, 0.f, 0.f};
            float d1[4] = {0.f, 0.f, 0.f, 0.f};
            #pragma unroll
            for (int ks = 0; ks < 4; ks++) {
                u32 b0 = bw[ks * 8 + t];
                u32 b1 = bw[ks * 8 + t + 4];
                mma16816(d0, af[0][ks], b0, b1);
                mma16816(d1, af[1][ks], b0, b1);
            }
            const int k0 = nt * 8 + 2 * t;           // cols of this thread
            const float2 ck = *(const float2*)(cbsqr + k0);
            // rows: wbase+g, wbase+g+8 (mt0); +16, +24 (mt1)
            float s0 = fmaf(-2.0f, d0[0], ck.x), s1 = fmaf(-2.0f, d0[1], ck.y);
            float s2 = fmaf(-2.0f, d0[2], ck.x), s3 = fmaf(-2.0f, d0[3], ck.y);
            float s4 = fmaf(-2.0f, d1[0], ck.x), s5 = fmaf(-2.0f, d1[1], ck.y);
            float s6 = fmaf(-2.0f, d1[2], ck.x), s7 = fmaf(-2.0f, d1[3], ck.y);
            const int cc = nt * 4 + t;
            u32 w0 = bf16x2(s1, s0);
            u32 w1 = bf16x2(s3, s2);
            u32 w2 = bf16x2(s5, s4);
            u32 w3 = bf16x2(s7, s6);
            sbuf[(wbase + g +  0) * SROW_U32 + cc] = w0;
            sbuf[(wbase + g +  8) * SROW_U32 + cc] = w1;
            sbuf[(wbase + g + 16) * SROW_U32 + cc] = w2;
            sbuf[(wbase + g + 24) * SROW_U32 + cc] = w3;
            // mins tracked on the bf16-rounded values (consistency with scan)
            mn0 = fminf(mn0, fminf(__uint_as_float(w0 << 16), __uint_as_float(w0 & 0xFFFF0000u)));
            mn1 = fminf(mn1, fminf(__uint_as_float(w1 << 16), __uint_as_float(w1 & 0xFFFF0000u)));
            mn2 = fminf(mn2, fminf(__uint_as_float(w2 << 16), __uint_as_float(w2 & 0xFFFF0000u)));
            mn3 = fminf(mn3, fminf(__uint_as_float(w3 << 16), __uint_as_float(w3 & 0xFFFF0000u)));
        }
        // combine mins across the 4 lanes of each quad
        #pragma unroll
        for (int d = 1; d < 4; d <<= 1) {
            mn0 = fminf(mn0, __shfl_xor_sync(0xffffffffu, mn0, d));
            mn1 = fminf(mn1, __shfl_xor_sync(0xffffffffu, mn1, d));
            mn2 = fminf(mn2, __shfl_xor_sync(0xffffffffu, mn2, d));
            mn3 = fminf(mn3, __shfl_xor_sync(0xffffffffu, mn3, d));
        }
        if (t == 0) {
            sminbuf[wbase + g +  0] = mn0;
            sminbuf[wbase + g +  8] = mn1;
            sminbuf[wbase + g + 16] = mn2;
            sminbuf[wbase + g + 24] = mn3;
        }
        __syncwarp();

        // ---- scan + exact refine (ascending k = 2c -> first-index argmin) --
        const float thresh =
            sminbuf[m] + fmaf(0.06f * cmax, sqrtf(xsqr), 2e-4f);
        const u32* srow = sbuf + m * SROW_U32;
        float best = 3.4028235e38f;
        int bestk = 0;
        for (int c = 0; c < 256; c++) {
            u32 w = srow[c];
            float lo = __uint_as_float(w << 16);
            float hi = __uint_as_float(w & 0xFFFF0000u);
            if (lo <= thresh) {
                int k = 2 * c;
                float d = exact_dist(cbg + (size_t)k * DD, x2, cbsqr[k] + xsqr);
                if (d < best) { best = d; bestk = k; }
            }
            if (hi <= thresh) {
                int k = 2 * c + 1;
                float d = exact_dist(cbg + (size_t)k * DD, x2, cbsqr[k] + xsqr);
                if (d < best) { best = d; bestk = k; }
            }
        }

        // ---- scatter winning f32 code row to both outputs (NCHW) ----
        const float4* code4 = (const float4*)(cbg + (size_t)bestk * DD);
        float* o1 = out + (size_t)b * (DD * HW) + s;
        float* o2 = o1 + (size_t)NVEC * DD;
        #pragma unroll
        for (int q = 0; q < 16; q++) {
            float4 w = code4[q];
            o1[(size_t)(4 * q + 0) * HW] = w.x;
            o1[(size_t)(4 * q + 1) * HW] = w.y;
            o1[(size_t)(4 * q + 2) * HW] = w.z;
            o1[(size_t)(4 * q + 3) * HW] = w.w;
            if (write2) {
                o2[(size_t)(4 * q + 0) * HW] = w.x;
                o2[(size_t)(4 * q + 1) * HW] = w.y;
                o2[(size_t)(4 * q + 2) * HW] = w.z;
                o2[(size_t)(4 * q + 3) * HW] = w.w;
            }
        }
        __syncwarp();   // sbuf/smin rows reused next tile (warp-private)
    }
}

extern "C" void kernel_launch(void* const* d_in, const int* in_sizes, int n_in,
                              void* d_out, int out_size) {
    const float* ze  = (const float*)d_in[0];   // z_e_x [32,64,64,64] f32
    const float* cbg = (const float*)d_in[1];   // codebook [512,64] f32
    float* out = (float*)d_out;
    const int write2 = (out_size >= 2 * NVEC * DD) ? 1 : 0;
    cudaFuncSetAttribute(vq_kernel, cudaFuncAttributeMaxDynamicSharedMemorySize,
                         SMEM_TOTAL);
    vq_kernel<<<GRID, NTH, SMEM_TOTAL>>>(ze, cbg, out, write2);
}

// round 14
// speedup vs baseline: 1.1330x; 1.1330x over previous
#include <cuda_runtime.h>
#include <cuda_bf16.h>
#include <cstdint>

#define KC 512
#define DD 64
#define HW 4096
#define NVEC 131072
#define NTH 128
#define MTILE 128
#define NTILES (NVEC / MTILE)        // 1024
#define GRID 128                     // 8 tiles per CTA, perfectly balanced
#define CAP 4096                     // worklist capacity (expected ~640 used)

// smem byte offsets
#define OFF_CBSQR  0                         // 512 f32 = 2048
#define OFF_SMIN   2048                      // 128 f32 = 512
#define OFF_MAXB   2560                      // 4
#define OFF_CNT    2564                      // 4
#define OFF_KEY    2624                      // 128 u64 = 1024 -> 3648
#define OFF_CB16   3648                      // 512*36*4 = 73728 -> 77376
#define OFF_A16    77376                     // 128*36*4 = 18432 -> 95808
#define OFF_WL     77376                     // overlays A16 (A is in regs by then)
#define OFF_SBUF   95808                     // 128*261*4 = 133632 -> 229440
#define SROW_U32   261                       // 256 data + 5 pad (gcd(5,32)=1)
#define CBROW_U32  36                        // 32 data + 4 pad (4g+t bank map)
#define SMEM_TOTAL 229440                    // <= 232448

typedef unsigned long long u64;
typedef unsigned int u32;

__device__ __forceinline__ u64 ffma2(u64 a, u64 b, u64 c) {
    u64 d;
    asm("fma.rn.f32x2 %0, %1, %2, %3;" : "=l"(d) : "l"(a), "l"(b), "l"(c));
    return d;
}
__device__ __forceinline__ u64 pk(float lo, float hi) {
    u64 d;
    asm("mov.b64 %0, {%1, %2};" : "=l"(d) : "f"(lo), "f"(hi));
    return d;
}
__device__ __forceinline__ void unpack2(u64 a, float& lo, float& hi) {
    asm("mov.b64 {%0, %1}, %2;" : "=f"(lo), "=f"(hi) : "l"(a));
}
__device__ __forceinline__ u32 bf16x2(float hi, float lo) {
    u32 w;
    asm("cvt.rn.bf16x2.f32 %0, %1, %2;" : "=r"(w) : "f"(hi), "f"(lo));
    return w;
}
// Scalar tree identical to round 1 (bit-exact vs reference; rel_err 0.0).
__device__ __forceinline__ float tree8(u64 a0, u64 a1, u64 a2, u64 a3) {
    float f0, f1, f2, f3, f4, f5, f6, f7;
    unpack2(a0, f0, f1); unpack2(a1, f2, f3);
    unpack2(a2, f4, f5); unpack2(a3, f6, f7);
    return ((f0 + f1) + (f2 + f3)) + ((f4 + f5) + (f6 + f7));
}
// Exact distance: byte-identical arithmetic to round 1 (4 chains, tree, fmaf).
__device__ __forceinline__ float exact_dist(const float* __restrict__ cbrow,
                                            const u64* x2, float ckxs) {
    u64 a0 = 0, a1 = 0, a2 = 0, a3 = 0;
    const float4* c4 = (const float4*)cbrow;
    #pragma unroll
    for (int j = 0; j < 8; j++) {
        float4 lo = c4[2 * j], hi = c4[2 * j + 1];
        a0 = ffma2(x2[4 * j + 0], pk(lo.x, lo.y), a0);
        a1 = ffma2(x2[4 * j + 1], pk(lo.z, lo.w), a1);
        a2 = ffma2(x2[4 * j + 2], pk(hi.x, hi.y), a2);
        a3 = ffma2(x2[4 * j + 3], pk(hi.z, hi.w), a3);
    }
    return fmaf(-2.0f, tree8(a0, a1, a2, a3), ckxs);
}
// HMMA m16n8k16 bf16 -> f32 (plain PTX, base sm_103 target OK)
__device__ __forceinline__ void mma16816(float* d, const u32* a, u32 b0, u32 b1) {
    asm volatile(
        "mma.sync.aligned.m16n8k16.row.col.f32.bf16.bf16.f32 "
        "{%0,%1,%2,%3}, {%4,%5,%6,%7}, {%8,%9}, {%0,%1,%2,%3};"
        : "+f"(d[0]), "+f"(d[1]), "+f"(d[2]), "+f"(d[3])
        : "r"(a[0]), "r"(a[1]), "r"(a[2]), "r"(a[3]), "r"(b0), "r"(b1));
}

__global__ void __launch_bounds__(NTH, 1)
vq_kernel(const float* __restrict__ ze, const float* __restrict__ cbg,
          float* __restrict__ out, int write2) {
    extern __shared__ char smem[];
    float* cbsqr   = (float*)(smem + OFF_CBSQR);
    float* sminbuf = (float*)(smem + OFF_SMIN);
    int*   maxb    = (int*)(smem + OFF_MAXB);
    int*   cnt     = (int*)(smem + OFF_CNT);
    u64*   key     = (u64*)(smem + OFF_KEY);    // [128]
    u32*   cb16    = (u32*)(smem + OFF_CB16);   // [512][36]
    u32*   a16     = (u32*)(smem + OFF_A16);    // [128][36] (overlaid by WL)
    u32*   wl      = (u32*)(smem + OFF_WL);     // [CAP]
    u32*   sbuf    = (u32*)(smem + OFF_SBUF);   // [128][261]

    const int tid = threadIdx.x;
    const int wid = tid >> 5;
    const int lane = tid & 31;
    const int g = lane >> 2;
    const int t = lane & 3;

    // ---- setup: codebook bf16 (padded rows), cbsqr, cmax ----
    if (tid == 0) *maxb = 0;
    __syncthreads();
    for (int idx = tid; idx < KC * 32; idx += NTH) {
        int row = idx >> 5, j = idx & 31;
        float lo = cbg[row * DD + 2 * j], hi = cbg[row * DD + 2 * j + 1];
        cb16[row * CBROW_U32 + j] = bf16x2(hi, lo);
    }
    for (int k = tid; k < KC; k += NTH) {
        const float* row = cbg + k * DD;
        float s = 0.f;
        #pragma unroll
        for (int d = 0; d < DD; d++) s = fmaf(row[d], row[d], s);
        cbsqr[k] = s;
        atomicMax(maxb, __float_as_int(s));   // s > 0: bits monotone
    }
    __syncthreads();
    const float cmax = sqrtf(__int_as_float(*maxb)) * 1.0002f;

    const int m = tid;
    const int wbase = wid * 32;

    for (int tile = blockIdx.x; tile < NTILES; tile += GRID) {
        const int n = tile * MTILE + m;
        const int b = n >> 12;
        const int s = n & 4095;
        const float* xp = ze + (size_t)b * (DD * HW) + s;

        // init per-tile shared state (visibility guaranteed by barrier (1))
        key[m] = ~0ull;
        if (tid == 0) *cnt = 0;

        // ---- load x (f32), xsqr (round-1 chain), pack regs, A row bf16 ----
        u64 x2[32];
        float xsqr = 0.f;
        #pragma unroll
        for (int j = 0; j < 32; j++) {
            float lo = xp[(size_t)(2 * j) * HW];
            float hi = xp[(size_t)(2 * j + 1) * HW];
            xsqr = fmaf(lo, lo, xsqr);
            xsqr = fmaf(hi, hi, xsqr);
            x2[j] = pk(lo, hi);
        }
        {
            u32* arow = a16 + m * CBROW_U32;
            #pragma unroll
            for (int jj = 0; jj < 32; jj++) {     // rotation: conflict-free STS
                int j = (jj + m) & 31;
                float lo, hi;
                unpack2(x2[j], lo, hi);
                arow[j] = bf16x2(hi, lo);
            }
        }
        __syncwarp();   // A rows warp-private

        // ---- register-resident A fragments ----
        u32 af[2][4][4];
        #pragma unroll
        for (int mt = 0; mt < 2; mt++) {
            const u32* r0 = a16 + (wbase + mt * 16 + g) * CBROW_U32;
            const u32* r1 = r0 + 8 * CBROW_U32;
            #pragma unroll
            for (int ks = 0; ks < 4; ks++) {
                af[mt][ks][0] = r0[ks * 8 + t];
                af[mt][ks][1] = r1[ks * 8 + t];
                af[mt][ks][2] = r0[ks * 8 + t + 4];
                af[mt][ks][3] = r1[ks * 8 + t + 4];
            }
        }
        __syncthreads();   // (1) A consumed (WL may overwrite) + init visible

        // ---- mma loop: 64 N-tiles of 8 codes; s = ck - 2 dot -> bf16 ----
        float mn0 = 3.4e38f, mn1 = 3.4e38f, mn2 = 3.4e38f, mn3 = 3.4e38f;
        #pragma unroll 2
        for (int nt = 0; nt < 64; nt++) {
            const u32* bw = cb16 + (nt * 8 + g) * CBROW_U32;
            float d0[4] = {0.f, 0.f, 0.f, 0.f};
            float d1[4] = {0.f, 0.f, 0.f, 0.f};
            #pragma unroll
            for (int ks = 0; ks < 4; ks++) {
                u32 b0 = bw[ks * 8 + t];
                u32 b1 = bw[ks * 8 + t + 4];
                mma16816(d0, af[0][ks], b0, b1);
                mma16816(d1, af[1][ks], b0, b1);
            }
            const int k0 = nt * 8 + 2 * t;
            const float2 ck = *(const float2*)(cbsqr + k0);
            float s0 = fmaf(-2.0f, d0[0], ck.x), s1 = fmaf(-2.0f, d0[1], ck.y);
            float s2 = fmaf(-2.0f, d0[2], ck.x), s3 = fmaf(-2.0f, d0[3], ck.y);
            float s4 = fmaf(-2.0f, d1[0], ck.x), s5 = fmaf(-2.0f, d1[1], ck.y);
            float s6 = fmaf(-2.0f, d1[2], ck.x), s7 = fmaf(-2.0f, d1[3], ck.y);
            const int cc = nt * 4 + t;
            u32 w0 = bf16x2(s1, s0);
            u32 w1 = bf16x2(s3, s2);
            u32 w2 = bf16x2(s5, s4);
            u32 w3 = bf16x2(s7, s6);
            sbuf[(wbase + g +  0) * SROW_U32 + cc] = w0;
            sbuf[(wbase + g +  8) * SROW_U32 + cc] = w1;
            sbuf[(wbase + g + 16) * SROW_U32 + cc] = w2;
            sbuf[(wbase + g + 24) * SROW_U32 + cc] = w3;
            mn0 = fminf(mn0, fminf(__uint_as_float(w0 << 16), __uint_as_float(w0 & 0xFFFF0000u)));
            mn1 = fminf(mn1, fminf(__uint_as_float(w1 << 16), __uint_as_float(w1 & 0xFFFF0000u)));
            mn2 = fminf(mn2, fminf(__uint_as_float(w2 << 16), __uint_as_float(w2 & 0xFFFF0000u)));
            mn3 = fminf(mn3, fminf(__uint_as_float(w3 << 16), __uint_as_float(w3 & 0xFFFF0000u)));
        }
        #pragma unroll
        for (int d = 1; d < 4; d <<= 1) {
            mn0 = fminf(mn0, __shfl_xor_sync(0xffffffffu, mn0, d));
            mn1 = fminf(mn1, __shfl_xor_sync(0xffffffffu, mn1, d));
            mn2 = fminf(mn2, __shfl_xor_sync(0xffffffffu, mn2, d));
            mn3 = fminf(mn3, __shfl_xor_sync(0xffffffffu, mn3, d));
        }
        if (t == 0) {
            sminbuf[wbase + g +  0] = mn0;
            sminbuf[wbase + g +  8] = mn1;
            sminbuf[wbase + g + 16] = mn2;
            sminbuf[wbase + g + 24] = mn3;
        }
        __syncwarp();

        // ---- scan own row: push candidates to CTA worklist (no refine) ----
        const float thresh =
            sminbuf[m] + fmaf(0.06f * cmax, sqrtf(xsqr), 2e-4f);
        const u32* srow = sbuf + m * SROW_U32;
        const u32 rowtag = (u32)m << 9;
        #pragma unroll 8
        for (int c = 0; c < 256; c++) {
            u32 w = srow[c];
            float lo = __uint_as_float(w << 16);
            float hi = __uint_as_float(w & 0xFFFF0000u);
            if (lo <= thresh) {
                int i = atomicAdd(cnt, 1);
                if (i < CAP) wl[i] = rowtag | (u32)(2 * c);
            }
            if (hi <= thresh) {
                int i = atomicAdd(cnt, 1);
                if (i < CAP) wl[i] = rowtag | (u32)(2 * c + 1);
            }
        }
        __syncthreads();   // (2) worklist complete

        const int count = *cnt;
        int bestk;
        if (count <= CAP) {
            // ---- batch-parallel exact refine: thread i -> entry i ----
            // key = (bits(dist)<<9)|k : dist>0 so bits order-isomorphic;
            // atomicMin gives exact first-index argmin among candidates
            // (window provably contains the true argmin and all exact ties).
            for (int i = tid; i < count; i += NTH) {
                u32 e = wl[i];
                int row = (int)(e >> 9);
                int k   = (int)(e & 511u);
                // x2 of that row lives in its owner thread; but dist needs
                // the OWNER's x. Entries are refined with shared x via sbuf?
                // No: refine must use row's x -> only owner has it. So keep
                // owner-computed path: entries carry this thread's rows only
                // when pushed... (see note) -- here e was pushed by thread
                // 'row' itself; we recompute with row's x gathered from ze.
                const int nn = tile * MTILE + row;
                const int bb = nn >> 12;
                const int ss = nn & 4095;
                const float* xq = ze + (size_t)bb * (DD * HW) + ss;
                u64 xx[32];
                float xs = 0.f;
                #pragma unroll
                for (int j = 0; j < 32; j++) {
                    float lo = xq[(size_t)(2 * j) * HW];
                    float hi = xq[(size_t)(2 * j + 1) * HW];
                    xs = fmaf(lo, lo, xs);
                    xs = fmaf(hi, hi, xs);
                    xx[j] = pk(lo, hi);
                }
                float d = exact_dist(cbg + (size_t)k * DD, xx, cbsqr[k] + xs);
                u64 kk = ((u64)((u32)__float_as_int(d)) << 9) | (u32)k;
                atomicMin((unsigned long long*)&key[row], kk);
            }
            __syncthreads();   // (3) keys final
            bestk = (int)(key[m] & 511u);
        } else {
            // overflow fallback (never expected): full exact first-index scan
            float best = 3.4028235e38f;
            bestk = 0;
            for (int k = 0; k < KC; k++) {
                float d = exact_dist(cbg + (size_t)k * DD, x2, cbsqr[k] + xsqr);
                if (d < best) { best = d; bestk = k; }
            }
            __syncthreads();
        }

        // ---- scatter winning f32 code row to both outputs (NCHW) ----
        const float4* code4 = (const float4*)(cbg + (size_t)bestk * DD);
        float* o1 = out + (size_t)b * (DD * HW) + s;
        float* o2 = o1 + (size_t)NVEC * DD;
        #pragma unroll
        for (int q = 0; q < 16; q++) {
            float4 w = code4[q];
            o1[(size_t)(4 * q + 0) * HW] = w.x;
            o1[(size_t)(4 * q + 1) * HW] = w.y;
            o1[(size_t)(4 * q + 2) * HW] = w.z;
            o1[(size_t)(4 * q + 3) * HW] = w.w;
            if (write2) {
                o2[(size_t)(4 * q + 0) * HW] = w.x;
                o2[(size_t)(4 * q + 1) * HW] = w.y;
                o2[(size_t)(4 * q + 2) * HW] = w.z;
                o2[(size_t)(4 * q + 3) * HW] = w.w;
            }
        }
        __syncthreads();   // (4) key/WL reads done before next tile's init
    }
}

extern "C" void kernel_launch(void* const* d_in, const int* in_sizes, int n_in,
                              void* d_out, int out_size) {
    const float* ze  = (const float*)d_in[0];   // z_e_x [32,64,64,64] f32
    const float* cbg = (const float*)d_in[1];   // codebook [512,64] f32
    float* out = (float*)d_out;
    const int write2 = (out_size >= 2 * NVEC * DD) ? 1 : 0;
    cudaFuncSetAttribute(vq_kernel, cudaFuncAttributeMaxDynamicSharedMemorySize,
                         SMEM_TOTAL);
    vq_kernel<<<GRID, NTH, SMEM_TOTAL>>>(ze, cbg, out, write2);
}

// round 15
// speedup vs baseline: 2.1608x; 1.9072x over previous
#include <cuda_runtime.h>
#include <cuda_bf16.h>
#include <cstdint>

#define KC 512
#define DD 64
#define HW 4096
#define NVEC 131072
#define NTH 256
#define MTILE 256
#define NTILES (NVEC / MTILE)        // 512
#define GRID 256                     // 2 tiles per CTA; 2 CTAs per SM
#define CAP 1000

#define CBROW 36                     // 32 data + cbsqr@32 + pad (4g+t bank map)
#define AROW  34                     // 32 data + thresh@32 + pad
// smem byte offsets
#define OFF_CB16 0                            // 512*36*4 = 73728
#define OFF_A16  73728                        // 256*34*4 = 34816 -> 108544
#define OFF_KEY  108544                       // 256 u64 = 2048   -> 110592
#define OFF_WL   110592                       // 1000 u32 = 4000  -> 114592
#define OFF_CNT  114592
#define OFF_MAXB 114596
#define SMEM_TOTAL 114688                     // 2 CTAs/SM: 2*(112K+1K) < 228K

typedef unsigned long long u64;
typedef unsigned int u32;

__device__ __forceinline__ u64 ffma2(u64 a, u64 b, u64 c) {
    u64 d;
    asm("fma.rn.f32x2 %0, %1, %2, %3;" : "=l"(d) : "l"(a), "l"(b), "l"(c));
    return d;
}
__device__ __forceinline__ u64 pk(float lo, float hi) {
    u64 d;
    asm("mov.b64 %0, {%1, %2};" : "=l"(d) : "f"(lo), "f"(hi));
    return d;
}
__device__ __forceinline__ void unpack2(u64 a, float& lo, float& hi) {
    asm("mov.b64 {%0, %1}, %2;" : "=f"(lo), "=f"(hi) : "l"(a));
}
__device__ __forceinline__ u32 bf16x2(float hi, float lo) {
    u32 w;
    asm("cvt.rn.bf16x2.f32 %0, %1, %2;" : "=r"(w) : "f"(hi), "f"(lo));
    return w;
}
// Scalar tree identical to round 1 (bit-exact vs reference; rel_err 0.0).
__device__ __forceinline__ float tree8(u64 a0, u64 a1, u64 a2, u64 a3) {
    float f0, f1, f2, f3, f4, f5, f6, f7;
    unpack2(a0, f0, f1); unpack2(a1, f2, f3);
    unpack2(a2, f4, f5); unpack2(a3, f6, f7);
    return ((f0 + f1) + (f2 + f3)) + ((f4 + f5) + (f6 + f7));
}
// Exact distance: byte-identical arithmetic to round 1 (4 chains, tree, fmaf).
__device__ __forceinline__ float exact_dist(const float* __restrict__ cbrow,
                                            const u64* x2, float ckxs) {
    u64 a0 = 0, a1 = 0, a2 = 0, a3 = 0;
    const float4* c4 = (const float4*)cbrow;
    #pragma unroll
    for (int j = 0; j < 8; j++) {
        float4 lo = c4[2 * j], hi = c4[2 * j + 1];
        a0 = ffma2(x2[4 * j + 0], pk(lo.x, lo.y), a0);
        a1 = ffma2(x2[4 * j + 1], pk(lo.z, lo.w), a1);
        a2 = ffma2(x2[4 * j + 2], pk(hi.x, hi.y), a2);
        a3 = ffma2(x2[4 * j + 3], pk(hi.z, hi.w), a3);
    }
    return fmaf(-2.0f, tree8(a0, a1, a2, a3), ckxs);
}
// Reload row's x with the round-1 chain (bit-exact; proven in R14).
__device__ __forceinline__ float load_x(const float* __restrict__ xq, u64* xx) {
    float xs = 0.f;
    #pragma unroll
    for (int j = 0; j < 32; j++) {
        float lo = xq[(size_t)(2 * j) * HW];
        float hi = xq[(size_t)(2 * j + 1) * HW];
        xs = fmaf(lo, lo, xs);
        xs = fmaf(hi, hi, xs);
        xx[j] = pk(lo, hi);
    }
    return xs;
}
// HMMA m16n8k16 bf16 -> f32 (plain PTX, base sm_103 target OK)
__device__ __forceinline__ void mma16816(float* d, const u32* a, u32 b0, u32 b1) {
    asm volatile(
        "mma.sync.aligned.m16n8k16.row.col.f32.bf16.bf16.f32 "
        "{%0,%1,%2,%3}, {%4,%5,%6,%7}, {%8,%9}, {%0,%1,%2,%3};"
        : "+f"(d[0]), "+f"(d[1]), "+f"(d[2]), "+f"(d[3])
        : "r"(a[0]), "r"(a[1]), "r"(a[2]), "r"(a[3]), "r"(b0), "r"(b1));
}

__global__ void __launch_bounds__(NTH, 2)
vq_kernel(const float* __restrict__ ze, const float* __restrict__ cbg,
          float* __restrict__ out, int write2) {
    extern __shared__ char smem[];
    u32*   cb16 = (u32*)(smem + OFF_CB16);   // [512][36], cbsqr at col 32
    u32*   a16  = (u32*)(smem + OFF_A16);    // [256][34], thresh at col 32
    float* a16f = (float*)(smem + OFF_A16);
    u64*   key  = (u64*)(smem + OFF_KEY);    // [256]
    u32*   wl   = (u32*)(smem + OFF_WL);     // [CAP]
    int*   cnt  = (int*)(smem + OFF_CNT);
    int*   maxb = (int*)(smem + OFF_MAXB);

    const int tid = threadIdx.x;
    const int wid = tid >> 5;
    const int lane = tid & 31;
    const int g = lane >> 2;
    const int t = lane & 3;
    const int wbase = wid * 32;
    const int m = tid;

    // ---- setup: codebook bf16 + cbsqr packed in row padding ----
    if (tid == 0) *maxb = 0;
    __syncthreads();
    for (int idx = tid; idx < KC * 32; idx += NTH) {
        int row = idx >> 5, j = idx & 31;
        float lo = cbg[row * DD + 2 * j], hi = cbg[row * DD + 2 * j + 1];
        cb16[row * CBROW + j] = bf16x2(hi, lo);
    }
    for (int k = tid; k < KC; k += NTH) {
        const float* row = cbg + k * DD;
        float s = 0.f;
        #pragma unroll
        for (int d = 0; d < DD; d++) s = fmaf(row[d], row[d], s);
        cb16[k * CBROW + 32] = __float_as_uint(s);
        atomicMax(maxb, __float_as_int(s));   // s > 0: bits monotone
    }
    __syncthreads();
    const float cmax = sqrtf(__int_as_float(*maxb)) * 1.0002f;

    for (int tile = blockIdx.x; tile < NTILES; tile += GRID) {
        const int btile = (tile * MTILE) >> 12;        // whole tile shares b
        const int stile = (tile * MTILE) & 4095;
        const float* xp = ze + (size_t)btile * (DD * HW) + stile + m;

        key[m] = ~0ull;
        if (tid == 0) *cnt = 0;

        // ---- load x (round-1 chain), write bf16 A row ----
        float xsqr = 0.f;
        {
            u32* arow = a16 + m * AROW;
            #pragma unroll
            for (int j = 0; j < 32; j++) {
                float lo = xp[(size_t)(2 * j) * HW];
                float hi = xp[(size_t)(2 * j + 1) * HW];
                xsqr = fmaf(lo, lo, xsqr);
                xsqr = fmaf(hi, hi, xsqr);
                arow[j] = bf16x2(hi, lo);
            }
        }
        __syncthreads();   // A visible; cnt/key init visible CTA-wide

        // ---- register A fragments (warp-private rows) ----
        u32 af[2][4][4];
        #pragma unroll
        for (int mt = 0; mt < 2; mt++) {
            const u32* r0 = a16 + (wbase + mt * 16 + g) * AROW;
            const u32* r1 = r0 + 8 * AROW;
            #pragma unroll
            for (int ks = 0; ks < 4; ks++) {
                af[mt][ks][0] = r0[ks * 8 + t];
                af[mt][ks][1] = r1[ks * 8 + t];
                af[mt][ks][2] = r0[ks * 8 + t + 4];
                af[mt][ks][3] = r1[ks * 8 + t + 4];
            }
        }

        // ---- pass A: min of raw f32 s = ck - 2 dot (no storage) ----
        float mn0 = 3.4e38f, mn1 = 3.4e38f, mn2 = 3.4e38f, mn3 = 3.4e38f;
        #pragma unroll 2
        for (int nt = 0; nt < 64; nt++) {
            const u32* bw = cb16 + (nt * 8 + g) * CBROW;
            float d0[4] = {0.f, 0.f, 0.f, 0.f};
            float d1[4] = {0.f, 0.f, 0.f, 0.f};
            #pragma unroll
            for (int ks = 0; ks < 4; ks++) {
                u32 b0 = bw[ks * 8 + t];
                u32 b1 = bw[ks * 8 + t + 4];
                mma16816(d0, af[0][ks], b0, b1);
                mma16816(d1, af[1][ks], b0, b1);
            }
            const int k0 = nt * 8 + 2 * t;
            float ckx = __uint_as_float(cb16[k0 * CBROW + 32]);
            float cky = __uint_as_float(cb16[(k0 + 1) * CBROW + 32]);
            mn0 = fminf(mn0, fminf(fmaf(-2.f, d0[0], ckx), fmaf(-2.f, d0[1], cky)));
            mn1 = fminf(mn1, fminf(fmaf(-2.f, d0[2], ckx), fmaf(-2.f, d0[3], cky)));
            mn2 = fminf(mn2, fminf(fmaf(-2.f, d1[0], ckx), fmaf(-2.f, d1[1], cky)));
            mn3 = fminf(mn3, fminf(fmaf(-2.f, d1[2], ckx), fmaf(-2.f, d1[3], cky)));
        }
        #pragma unroll
        for (int d = 1; d < 4; d <<= 1) {
            mn0 = fminf(mn0, __shfl_xor_sync(0xffffffffu, mn0, d));
            mn1 = fminf(mn1, __shfl_xor_sync(0xffffffffu, mn1, d));
            mn2 = fminf(mn2, __shfl_xor_sync(0xffffffffu, mn2, d));
            mn3 = fminf(mn3, __shfl_xor_sync(0xffffffffu, mn3, d));
        }
        if (t == 0) {
            a16f[(wbase + g +  0) * AROW + 32] = mn0;
            a16f[(wbase + g +  8) * AROW + 32] = mn1;
            a16f[(wbase + g + 16) * AROW + 32] = mn2;
            a16f[(wbase + g + 24) * AROW + 32] = mn3;
        }
        __syncwarp();
        // row m's threshold (margin proven in R13/R14; pass-A min is raw f32,
        // strictly tighter than the bf16-rounded bound the margin covers)
        {
            float rowmin = a16f[m * AROW + 32];
            a16f[m * AROW + 32] =
                rowmin + fmaf(0.06f * cmax, sqrtf(xsqr), 2e-4f);
        }
        __syncwarp();
        const float th0 = a16f[(wbase + g +  0) * AROW + 32];
        const float th1 = a16f[(wbase + g +  8) * AROW + 32];
        const float th2 = a16f[(wbase + g + 16) * AROW + 32];
        const float th3 = a16f[(wbase + g + 24) * AROW + 32];

        // ---- pass B: identical MMA recompute; push candidates ----
        #pragma unroll 2
        for (int nt = 0; nt < 64; nt++) {
            const u32* bw = cb16 + (nt * 8 + g) * CBROW;
            float d0[4] = {0.f, 0.f, 0.f, 0.f};
            float d1[4] = {0.f, 0.f, 0.f, 0.f};
            #pragma unroll
            for (int ks = 0; ks < 4; ks++) {
                u32 b0 = bw[ks * 8 + t];
                u32 b1 = bw[ks * 8 + t + 4];
                mma16816(d0, af[0][ks], b0, b1);
                mma16816(d1, af[1][ks], b0, b1);
            }
            const int k0 = nt * 8 + 2 * t;
            float ckx = __uint_as_float(cb16[k0 * CBROW + 32]);
            float cky = __uint_as_float(cb16[(k0 + 1) * CBROW + 32]);
            float s0 = fmaf(-2.f, d0[0], ckx), s1 = fmaf(-2.f, d0[1], cky);
            float s2 = fmaf(-2.f, d0[2], ckx), s3 = fmaf(-2.f, d0[3], cky);
            float s4 = fmaf(-2.f, d1[0], ckx), s5 = fmaf(-2.f, d1[1], cky);
            float s6 = fmaf(-2.f, d1[2], ckx), s7 = fmaf(-2.f, d1[3], cky);
            #define PUSH(cond, row, kk)                                     \
                if (cond) {                                                 \
                    int i = atomicAdd(cnt, 1);                              \
                    if (i < CAP) wl[i] = ((u32)(row) << 9) | (u32)(kk);     \
                }
            PUSH(s0 <= th0, wbase + g,      k0);
            PUSH(s1 <= th0, wbase + g,      k0 + 1);
            PUSH(s2 <= th1, wbase + g + 8,  k0);
            PUSH(s3 <= th1, wbase + g + 8,  k0 + 1);
            PUSH(s4 <= th2, wbase + g + 16, k0);
            PUSH(s5 <= th2, wbase + g + 16, k0 + 1);
            PUSH(s6 <= th3, wbase + g + 24, k0);
            PUSH(s7 <= th3, wbase + g + 24, k0 + 1);
            #undef PUSH
        }
        __syncthreads();   // worklist complete

        const int count = *cnt;
        if (count <= CAP) {
            // batch-parallel exact refine (bit-exact; key order-isomorphic,
            // ties -> smaller k = first-index argmin; window contains truth)
            for (int i = tid; i < count; i += NTH) {
                u32 e = wl[i];
                int row = (int)(e >> 9);
                int k   = (int)(e & 511u);
                u64 xx[32];
                float xs = load_x(ze + (size_t)btile * (DD * HW) + stile + row, xx);
                float ck = __uint_as_float(cb16[k * CBROW + 32]);
                float d  = exact_dist(cbg + (size_t)k * DD, xx, ck + xs);
                u64 kk = ((u64)((u32)__float_as_int(d)) << 9) | (u32)k;
                atomicMin((unsigned long long*)&key[row], kk);
            }
        } else {
            // overflow fallback (never expected): full exact scan, own row
            u64 xx[32];
            float xs = load_x(xp, xx);
            float best = 3.4028235e38f;
            int bestk = 0;
            for (int k = 0; k < KC; k++) {
                float ck = __uint_as_float(cb16[k * CBROW + 32]);
                float d = exact_dist(cbg + (size_t)k * DD, xx, ck + xs);
                if (d < best) { best = d; bestk = k; }
            }
            key[m] = ((u64)((u32)__float_as_int(best)) << 9) | (u32)bestk;
        }
        __syncthreads();   // keys final

        // ---- scatter winning f32 code row to both outputs (NCHW) ----
        const int bestk = (int)(key[m] & 511u);
        const float4* code4 = (const float4*)(cbg + (size_t)bestk * DD);
        float* o1 = out + (size_t)btile * (DD * HW) + stile + m;
        float* o2 = o1 + (size_t)NVEC * DD;
        #pragma unroll
        for (int q = 0; q < 16; q++) {
            float4 w = code4[q];
            o1[(size_t)(4 * q + 0) * HW] = w.x;
            o1[(size_t)(4 * q + 1) * HW] = w.y;
            o1[(size_t)(4 * q + 2) * HW] = w.z;
            o1[(size_t)(4 * q + 3) * HW] = w.w;
            if (write2) {
                o2[(size_t)(4 * q + 0) * HW] = w.x;
                o2[(size_t)(4 * q + 1) * HW] = w.y;
                o2[(size_t)(4 * q + 2) * HW] = w.z;
                o2[(size_t)(4 * q + 3) * HW] = w.w;
            }
        }
        __syncthreads();   // key/wl reads done before next tile's init
    }
}

extern "C" void kernel_launch(void* const* d_in, const int* in_sizes, int n_in,
                              void* d_out, int out_size) {
    const float* ze  = (const float*)d_in[0];   // z_e_x [32,64,64,64] f32
    const float* cbg = (const float*)d_in[1];   // codebook [512,64] f32
    float* out = (float*)d_out;
    const int write2 = (out_size >= 2 * NVEC * DD) ? 1 : 0;
    cudaFuncSetAttribute(vq_kernel, cudaFuncAttributeMaxDynamicSharedMemorySize,
                         SMEM_TOTAL);
    vq_kernel<<<GRID, NTH, SMEM_TOTAL>>>(ze, cbg, out, write2);
}